// round 8
// baseline (speedup 1.0000x reference)
#include <cuda_runtime.h>
#include <cstdint>

#define B_  16
#define Q_  256
#define K_  256
#define H_  256
#define DV_ 256

__device__ float g_qp[B_ * Q_ * H_];
__device__ float g_kp[B_ * K_ * H_];
__device__ float g_scores[B_ * Q_ * K_];

__device__ __forceinline__ float tanh_fast(float x) {
    float y;
    asm("tanh.approx.f32 %0, %1;" : "=f"(y) : "f"(x));
    return y;
}

// ---------------------------------------------------------------------------
// Kernel 1: projection GEMM  C[M,256] = A[M,256] * W[256,256]^T  (R1 exact)
// NOTE: launched TWICE (q then k). Merging into one grid.z=2 launch measured
// 2x slower (R2-R4) — do not merge.
// ---------------------------------------------------------------------------
__global__ __launch_bounds__(256) void proj_gemm(const float* __restrict__ A,
                                                 const float* __restrict__ W,
                                                 int sel) {
    constexpr int BM = 64, BN = 64, BK = 32;
    __shared__ float As[BK][BM + 4];
    __shared__ float Bs[BK][BN + 4];

    float* __restrict__ C = sel ? g_kp : g_qp;

    const int tid = threadIdx.x;
    const int m0 = blockIdx.y * BM;
    const int n0 = blockIdx.x * BN;
    const int ty = tid >> 4;
    const int tx = tid & 15;

    float acc[4][4];
#pragma unroll
    for (int i = 0; i < 4; i++)
#pragma unroll
        for (int j = 0; j < 4; j++) acc[i][j] = 0.0f;

    const int lr = tid >> 3;
    const int lc = (tid & 7) * 4;

    for (int kt = 0; kt < H_; kt += BK) {
        float4 a0 = *(const float4*)&A[(m0 + lr) * H_ + kt + lc];
        float4 a1 = *(const float4*)&A[(m0 + lr + 32) * H_ + kt + lc];
        float4 b0 = *(const float4*)&W[(n0 + lr) * H_ + kt + lc];
        float4 b1 = *(const float4*)&W[(n0 + lr + 32) * H_ + kt + lc];

        As[lc + 0][lr] = a0.x; As[lc + 1][lr] = a0.y;
        As[lc + 2][lr] = a0.z; As[lc + 3][lr] = a0.w;
        As[lc + 0][lr + 32] = a1.x; As[lc + 1][lr + 32] = a1.y;
        As[lc + 2][lr + 32] = a1.z; As[lc + 3][lr + 32] = a1.w;
        Bs[lc + 0][lr] = b0.x; Bs[lc + 1][lr] = b0.y;
        Bs[lc + 2][lr] = b0.z; Bs[lc + 3][lr] = b0.w;
        Bs[lc + 0][lr + 32] = b1.x; Bs[lc + 1][lr + 32] = b1.y;
        Bs[lc + 2][lr + 32] = b1.z; Bs[lc + 3][lr + 32] = b1.w;

        __syncthreads();

#pragma unroll
        for (int kk = 0; kk < BK; kk++) {
            float a[4], b[4];
#pragma unroll
            for (int i = 0; i < 4; i++) a[i] = As[kk][ty * 4 + i];
#pragma unroll
            for (int j = 0; j < 4; j++) b[j] = Bs[kk][tx * 4 + j];
#pragma unroll
            for (int i = 0; i < 4; i++)
#pragma unroll
                for (int j = 0; j < 4; j++) acc[i][j] += a[i] * b[j];
        }
        __syncthreads();
    }

#pragma unroll
    for (int i = 0; i < 4; i++) {
        float4 v;
        v.x = acc[i][0]; v.y = acc[i][1]; v.z = acc[i][2]; v.w = acc[i][3];
        *(float4*)&C[(m0 + ty * 4 + i) * H_ + n0 + tx * 4] = v;
    }
}

// ---------------------------------------------------------------------------
// Kernel 2: scores — R1 fp32 MUFU version; epilogue stores as float2.
// ---------------------------------------------------------------------------
__global__ __launch_bounds__(256) void scores_kernel(const float* __restrict__ wv) {
    const int b = blockIdx.z;
    const int q0 = blockIdx.y * 32;
    const int k0 = blockIdx.x * 32;

    __shared__ float qs[32][33];
    __shared__ float ks[32][33];
    __shared__ float ws[H_];

    const int tid = threadIdx.x;
    ws[tid] = wv[tid];

    const int ty = tid >> 4;
    const int tx = tid & 15;

    const float* qbase = g_qp + (b * Q_ + q0) * H_;
    const float* kbase = g_kp + (b * K_ + k0) * H_;

    float a00 = 0.f, a01 = 0.f, a10 = 0.f, a11 = 0.f;

    const int lr = tid >> 5;
    const int lc = tid & 31;

    for (int hc = 0; hc < H_; hc += 32) {
        __syncthreads();
#pragma unroll
        for (int rr = 0; rr < 4; rr++) {
            int row = lr + rr * 8;
            qs[row][lc] = qbase[row * H_ + hc + lc];
            ks[row][lc] = kbase[row * H_ + hc + lc];
        }
        __syncthreads();

#pragma unroll
        for (int hh = 0; hh < 32; hh++) {
            float w = ws[hc + hh];
            float qv0 = qs[ty * 2 + 0][hh];
            float qv1 = qs[ty * 2 + 1][hh];
            float kv0 = ks[tx * 2 + 0][hh];
            float kv1 = ks[tx * 2 + 1][hh];
            a00 += w * tanh_fast(qv0 + kv0);
            a01 += w * tanh_fast(qv0 + kv1);
            a10 += w * tanh_fast(qv1 + kv0);
            a11 += w * tanh_fast(qv1 + kv1);
        }
    }

    float* sbase = g_scores + (b * Q_ + q0) * K_ + k0;
    *(float2*)&sbase[(ty * 2 + 0) * K_ + tx * 2] = make_float2(a00, a01);
    *(float2*)&sbase[(ty * 2 + 1) * K_ + tx * 2] = make_float2(a10, a11);
}

// ---------------------------------------------------------------------------
// Kernel 3: fused softmax + AV GEMM.
// Block = 32 q-rows x 64 dv-cols. P rows (32x256) loaded to smem ONCE,
// softmaxed in place, then GEMM over V tiles (proj_gemm-style loop).
// Grid (DV/64=4, M/32=128) = 512 blocks.
// ---------------------------------------------------------------------------
__global__ __launch_bounds__(256) void av_softmax(const float* __restrict__ V,
                                                  float* __restrict__ out) {
    constexpr int BK = 32;
    __shared__ __align__(16) float Ps[32][260];   // 33.3 KB
    __shared__ __align__(16) float Bs[BK][68];    // 8.7 KB

    const int tid = threadIdx.x;
    const int m0 = blockIdx.y * 32;               // global q-row base
    const int n0 = blockIdx.x * 64;               // dv col base
    const int b  = m0 >> 8;                       // 256 rows per batch

    const float* __restrict__ P  = g_scores;
    const float* __restrict__ Vb = V + (size_t)b * K_ * DV_;

    // ---- load P rows into smem (32 x 256), fully coalesced ----
#pragma unroll
    for (int i = tid; i < 32 * 64; i += 256) {    // 2048 float4s
        const int r = i >> 6;
        const int c = (i & 63) << 2;
        *(float4*)&Ps[r][c] = *(const float4*)&P[(size_t)(m0 + r) * K_ + c];
    }
    __syncthreads();

    // ---- softmax in smem: warp w handles rows 4w..4w+3 ----
    const int w = tid >> 5;
    const int lane = tid & 31;
#pragma unroll
    for (int j = 0; j < 4; j++) {
        const int r = w * 4 + j;
        float4 v0 = *(const float4*)&Ps[r][lane * 4];
        float4 v1 = *(const float4*)&Ps[r][128 + lane * 4];
        float mx = fmaxf(fmaxf(fmaxf(v0.x, v0.y), fmaxf(v0.z, v0.w)),
                         fmaxf(fmaxf(v1.x, v1.y), fmaxf(v1.z, v1.w)));
#pragma unroll
        for (int off = 16; off; off >>= 1)
            mx = fmaxf(mx, __shfl_xor_sync(0xffffffffu, mx, off));
        v0.x = __expf(v0.x - mx); v0.y = __expf(v0.y - mx);
        v0.z = __expf(v0.z - mx); v0.w = __expf(v0.w - mx);
        v1.x = __expf(v1.x - mx); v1.y = __expf(v1.y - mx);
        v1.z = __expf(v1.z - mx); v1.w = __expf(v1.w - mx);
        float s = (v0.x + v0.y + v0.z + v0.w) + (v1.x + v1.y + v1.z + v1.w);
#pragma unroll
        for (int off = 16; off; off >>= 1)
            s += __shfl_xor_sync(0xffffffffu, s, off);
        const float inv = 1.0f / s;
        v0.x *= inv; v0.y *= inv; v0.z *= inv; v0.w *= inv;
        v1.x *= inv; v1.y *= inv; v1.z *= inv; v1.w *= inv;
        *(float4*)&Ps[r][lane * 4] = v0;
        *(float4*)&Ps[r][128 + lane * 4] = v1;
    }
    __syncthreads();

    // ---- GEMM: out[32 x 64] = Ps[32 x 256] * Vb[256 x 64-slice] ----
    const int ty = tid >> 4;        // 0..15 -> rows ty*2, ty*2+1
    const int tx = tid & 15;        // 0..15 -> cols tx*4..+3
    const int vr = tid >> 3;        // 0..31 (V k-row within tile)
    const int vc = (tid & 7) * 8;   // 0..56

    float acc[2][4];
#pragma unroll
    for (int i = 0; i < 2; i++)
#pragma unroll
        for (int j = 0; j < 4; j++) acc[i][j] = 0.f;

    for (int kt = 0; kt < K_; kt += BK) {
        const float* vrow = &Vb[(size_t)(kt + vr) * DV_ + n0 + vc];
        *(float4*)&Bs[vr][vc]     = *(const float4*)&vrow[0];
        *(float4*)&Bs[vr][vc + 4] = *(const float4*)&vrow[4];
        __syncthreads();

#pragma unroll
        for (int kk = 0; kk < BK; kk++) {
            float a0 = Ps[ty * 2 + 0][kt + kk];
            float a1 = Ps[ty * 2 + 1][kt + kk];
            float bb[4];
#pragma unroll
            for (int j = 0; j < 4; j++) bb[j] = Bs[kk][tx * 4 + j];
#pragma unroll
            for (int j = 0; j < 4; j++) {
                acc[0][j] += a0 * bb[j];
                acc[1][j] += a1 * bb[j];
            }
        }
        __syncthreads();
    }

#pragma unroll
    for (int i = 0; i < 2; i++) {
        *(float4*)&out[(size_t)(m0 + ty * 2 + i) * DV_ + n0 + tx * 4] =
            make_float4(acc[i][0], acc[i][1], acc[i][2], acc[i][3]);
    }
}

// ---------------------------------------------------------------------------
extern "C" void kernel_launch(void* const* d_in, const int* in_sizes, int n_in,
                              void* d_out, int out_size) {
    const float* queries = (const float*)d_in[0];
    const float* keys    = (const float*)d_in[1];
    const float* values  = (const float*)d_in[2];
    const float* W_q     = (const float*)d_in[3];
    const float* W_k     = (const float*)d_in[4];
    const float* w_v     = (const float*)d_in[5];
    float* out = (float*)d_out;

    dim3 gproj(H_ / 64, (B_ * Q_) / 64);
    proj_gemm<<<gproj, 256>>>(queries, W_q, 0);
    proj_gemm<<<gproj, 256>>>(keys,    W_k, 1);

    dim3 gscores(K_ / 32, Q_ / 32, B_);
    scores_kernel<<<gscores, 256>>>(w_v);

    dim3 gav(DV_ / 64, (B_ * Q_) / 32);
    av_softmax<<<gav, 256>>>(values, out);
}

// round 9
// speedup vs baseline: 1.0385x; 1.0385x over previous
#include <cuda_runtime.h>
#include <cstdint>

#define B_  16
#define Q_  256
#define K_  256
#define H_  256
#define DV_ 256

__device__ float g_qp[B_ * Q_ * H_];
__device__ float g_kp[B_ * K_ * H_];
__device__ float g_scores[B_ * Q_ * K_];

__device__ __forceinline__ float tanh_fast(float x) {
    float y;
    asm("tanh.approx.f32 %0, %1;" : "=f"(y) : "f"(x));
    return y;
}

// ---------------------------------------------------------------------------
// Kernel 1: projection GEMM  C[M,256] = A[M,256] * W[256,256]^T  (R1 exact)
// Launched twice; merging measured 2x slower (R2-R4).
// ---------------------------------------------------------------------------
__global__ __launch_bounds__(256) void proj_gemm(const float* __restrict__ A,
                                                 const float* __restrict__ W,
                                                 int sel) {
    constexpr int BM = 64, BN = 64, BK = 32;
    __shared__ float As[BK][BM + 4];
    __shared__ float Bs[BK][BN + 4];

    float* __restrict__ C = sel ? g_kp : g_qp;

    const int tid = threadIdx.x;
    const int m0 = blockIdx.y * BM;
    const int n0 = blockIdx.x * BN;
    const int ty = tid >> 4;
    const int tx = tid & 15;

    float acc[4][4];
#pragma unroll
    for (int i = 0; i < 4; i++)
#pragma unroll
        for (int j = 0; j < 4; j++) acc[i][j] = 0.0f;

    const int lr = tid >> 3;
    const int lc = (tid & 7) * 4;

    for (int kt = 0; kt < H_; kt += BK) {
        float4 a0 = *(const float4*)&A[(m0 + lr) * H_ + kt + lc];
        float4 a1 = *(const float4*)&A[(m0 + lr + 32) * H_ + kt + lc];
        float4 b0 = *(const float4*)&W[(n0 + lr) * H_ + kt + lc];
        float4 b1 = *(const float4*)&W[(n0 + lr + 32) * H_ + kt + lc];

        As[lc + 0][lr] = a0.x; As[lc + 1][lr] = a0.y;
        As[lc + 2][lr] = a0.z; As[lc + 3][lr] = a0.w;
        As[lc + 0][lr + 32] = a1.x; As[lc + 1][lr + 32] = a1.y;
        As[lc + 2][lr + 32] = a1.z; As[lc + 3][lr + 32] = a1.w;
        Bs[lc + 0][lr] = b0.x; Bs[lc + 1][lr] = b0.y;
        Bs[lc + 2][lr] = b0.z; Bs[lc + 3][lr] = b0.w;
        Bs[lc + 0][lr + 32] = b1.x; Bs[lc + 1][lr + 32] = b1.y;
        Bs[lc + 2][lr + 32] = b1.z; Bs[lc + 3][lr + 32] = b1.w;

        __syncthreads();

#pragma unroll
        for (int kk = 0; kk < BK; kk++) {
            float a[4], b[4];
#pragma unroll
            for (int i = 0; i < 4; i++) a[i] = As[kk][ty * 4 + i];
#pragma unroll
            for (int j = 0; j < 4; j++) b[j] = Bs[kk][tx * 4 + j];
#pragma unroll
            for (int i = 0; i < 4; i++)
#pragma unroll
                for (int j = 0; j < 4; j++) acc[i][j] += a[i] * b[j];
        }
        __syncthreads();
    }

#pragma unroll
    for (int i = 0; i < 4; i++) {
        float4 v;
        v.x = acc[i][0]; v.y = acc[i][1]; v.z = acc[i][2]; v.w = acc[i][3];
        *(float4*)&C[(m0 + ty * 4 + i) * H_ + n0 + tx * 4] = v;
    }
}

// ---------------------------------------------------------------------------
// Kernel 2: scores — R1 fp32 MUFU version (at the MUFU floor).
// ---------------------------------------------------------------------------
__global__ __launch_bounds__(256) void scores_kernel(const float* __restrict__ wv) {
    const int b = blockIdx.z;
    const int q0 = blockIdx.y * 32;
    const int k0 = blockIdx.x * 32;

    __shared__ float qs[32][33];
    __shared__ float ks[32][33];
    __shared__ float ws[H_];

    const int tid = threadIdx.x;
    ws[tid] = wv[tid];

    const int ty = tid >> 4;
    const int tx = tid & 15;

    const float* qbase = g_qp + (b * Q_ + q0) * H_;
    const float* kbase = g_kp + (b * K_ + k0) * H_;

    float a00 = 0.f, a01 = 0.f, a10 = 0.f, a11 = 0.f;

    const int lr = tid >> 5;
    const int lc = tid & 31;

    for (int hc = 0; hc < H_; hc += 32) {
        __syncthreads();
#pragma unroll
        for (int rr = 0; rr < 4; rr++) {
            int row = lr + rr * 8;
            qs[row][lc] = qbase[row * H_ + hc + lc];
            ks[row][lc] = kbase[row * H_ + hc + lc];
        }
        __syncthreads();

#pragma unroll
        for (int hh = 0; hh < 32; hh++) {
            float w = ws[hc + hh];
            float qv0 = qs[ty * 2 + 0][hh];
            float qv1 = qs[ty * 2 + 1][hh];
            float kv0 = ks[tx * 2 + 0][hh];
            float kv1 = ks[tx * 2 + 1][hh];
            a00 += w * tanh_fast(qv0 + kv0);
            a01 += w * tanh_fast(qv0 + kv1);
            a10 += w * tanh_fast(qv1 + kv0);
            a11 += w * tanh_fast(qv1 + kv1);
        }
    }

    float* sbase = g_scores + (b * Q_ + q0) * K_ + k0;
    *(float2*)&sbase[(ty * 2 + 0) * K_ + tx * 2] = make_float2(a00, a01);
    *(float2*)&sbase[(ty * 2 + 1) * K_ + tx * 2] = make_float2(a10, a11);
}

// ---------------------------------------------------------------------------
// Kernel 3: fused softmax + AV GEMM (proper 4x4 thread tile).
// Block = 128 threads, 32 q-rows x 64 dv-cols. P strip (32x256) in smem once,
// softmaxed in place, then proj-style tiled GEMM over V.
// Grid (DV/64=4, M/32=128) = 512 blocks. Static smem ~41KB -> 4 blocks/SM.
// ---------------------------------------------------------------------------
__global__ __launch_bounds__(128) void av_softmax2(const float* __restrict__ V,
                                                   float* __restrict__ out) {
    constexpr int BK = 32;
    __shared__ __align__(16) float Ps[32][260];   // 33.3 KB
    __shared__ __align__(16) float Bs[BK][68];    // 8.7 KB

    const int tid = threadIdx.x;
    const int m0 = blockIdx.y * 32;
    const int n0 = blockIdx.x * 64;
    const int b  = m0 >> 8;

    const float* __restrict__ P  = g_scores;
    const float* __restrict__ Vb = V + (size_t)b * K_ * DV_;

    // ---- load P strip (32 x 256) coalesced ----
#pragma unroll
    for (int i = tid; i < 32 * 64; i += 128) {
        const int r = i >> 6;
        const int c = (i & 63) << 2;
        *(float4*)&Ps[r][c] = *(const float4*)&P[(size_t)(m0 + r) * K_ + c];
    }
    __syncthreads();

    // ---- softmax in smem: 4 warps x 8 rows ----
    const int w = tid >> 5;
    const int lane = tid & 31;
#pragma unroll
    for (int j = 0; j < 8; j++) {
        const int r = w * 8 + j;
        float4 v0 = *(const float4*)&Ps[r][lane * 4];
        float4 v1 = *(const float4*)&Ps[r][128 + lane * 4];
        float mx = fmaxf(fmaxf(fmaxf(v0.x, v0.y), fmaxf(v0.z, v0.w)),
                         fmaxf(fmaxf(v1.x, v1.y), fmaxf(v1.z, v1.w)));
#pragma unroll
        for (int off = 16; off; off >>= 1)
            mx = fmaxf(mx, __shfl_xor_sync(0xffffffffu, mx, off));
        v0.x = __expf(v0.x - mx); v0.y = __expf(v0.y - mx);
        v0.z = __expf(v0.z - mx); v0.w = __expf(v0.w - mx);
        v1.x = __expf(v1.x - mx); v1.y = __expf(v1.y - mx);
        v1.z = __expf(v1.z - mx); v1.w = __expf(v1.w - mx);
        float s = (v0.x + v0.y + v0.z + v0.w) + (v1.x + v1.y + v1.z + v1.w);
#pragma unroll
        for (int off = 16; off; off >>= 1)
            s += __shfl_xor_sync(0xffffffffu, s, off);
        const float inv = 1.0f / s;
        v0.x *= inv; v0.y *= inv; v0.z *= inv; v0.w *= inv;
        v1.x *= inv; v1.y *= inv; v1.z *= inv; v1.w *= inv;
        *(float4*)&Ps[r][lane * 4] = v0;
        *(float4*)&Ps[r][128 + lane * 4] = v1;
    }
    __syncthreads();

    // ---- GEMM: out[32 x 64] = Ps[32 x 256] * Vb[256 x 64-slice] ----
    const int ty = tid >> 4;        // 0..7  -> rows ty*4..+3
    const int tx = tid & 15;        // 0..15 -> cols tx*4..+3
    const int vr = tid >> 2;        // 0..31 (V k-row within tile)
    const int vc = (tid & 3) * 16;  // 0,16,32,48

    float acc[4][4];
#pragma unroll
    for (int i = 0; i < 4; i++)
#pragma unroll
        for (int j = 0; j < 4; j++) acc[i][j] = 0.f;

    for (int kt = 0; kt < K_; kt += BK) {
        const float* vrow = &Vb[(size_t)(kt + vr) * DV_ + n0 + vc];
        float4 r0 = *(const float4*)&vrow[0];
        float4 r1 = *(const float4*)&vrow[4];
        float4 r2 = *(const float4*)&vrow[8];
        float4 r3 = *(const float4*)&vrow[12];
        *(float4*)&Bs[vr][vc + 0]  = r0;
        *(float4*)&Bs[vr][vc + 4]  = r1;
        *(float4*)&Bs[vr][vc + 8]  = r2;
        *(float4*)&Bs[vr][vc + 12] = r3;
        __syncthreads();

#pragma unroll
        for (int kk = 0; kk < BK; kk++) {
            float a[4], bb[4];
#pragma unroll
            for (int i = 0; i < 4; i++) a[i] = Ps[ty * 4 + i][kt + kk];
#pragma unroll
            for (int j = 0; j < 4; j++) bb[j] = Bs[kk][tx * 4 + j];
#pragma unroll
            for (int i = 0; i < 4; i++)
#pragma unroll
                for (int j = 0; j < 4; j++) acc[i][j] += a[i] * bb[j];
        }
        __syncthreads();
    }

#pragma unroll
    for (int i = 0; i < 4; i++) {
        *(float4*)&out[(size_t)(m0 + ty * 4 + i) * DV_ + n0 + tx * 4] =
            make_float4(acc[i][0], acc[i][1], acc[i][2], acc[i][3]);
    }
}

// ---------------------------------------------------------------------------
extern "C" void kernel_launch(void* const* d_in, const int* in_sizes, int n_in,
                              void* d_out, int out_size) {
    const float* queries = (const float*)d_in[0];
    const float* keys    = (const float*)d_in[1];
    const float* values  = (const float*)d_in[2];
    const float* W_q     = (const float*)d_in[3];
    const float* W_k     = (const float*)d_in[4];
    const float* w_v     = (const float*)d_in[5];
    float* out = (float*)d_out;

    dim3 gproj(H_ / 64, (B_ * Q_) / 64);
    proj_gemm<<<gproj, 256>>>(queries, W_q, 0);
    proj_gemm<<<gproj, 256>>>(keys,    W_k, 1);

    dim3 gscores(K_ / 32, Q_ / 32, B_);
    scores_kernel<<<gscores, 256>>>(w_v);

    dim3 gav(DV_ / 64, (B_ * Q_) / 32);
    av_softmax2<<<gav, 128>>>(values, out);
}